// round 1
// baseline (speedup 1.0000x reference)
#include <cuda_runtime.h>
#include <cuda_bf16.h>

// ---------------------------------------------------------------------------
// LiteMLA block, fp32 baseline.
// x(8,256,64,64) -> qkv GEMM(768x256) -> dw5x5 -> grouped pw(96 x 8->8)
//  -> relu linear attention (64 heads, dim 8) -> proj GEMM(256x512) + BN
// ---------------------------------------------------------------------------

#define B_   8
#define HWN  4096      // 64*64
#define C3   768
#define CATT 512

// Scratch (static device globals; no allocation allowed)
__device__ float g_qkv[B_ * C3 * HWN];   // 100.7 MB
__device__ float g_dw [B_ * C3 * HWN];   // 100.7 MB
__device__ float g_pw [B_ * C3 * HWN];   // 100.7 MB
__device__ float g_att[B_ * CATT * HWN]; //  67.1 MB

// ---------------------------------------------------------------------------
// Classic 128x128x8 SGEMM. C[b] = A(MxK) * Bsrc[b](KxN); optional BN epilogue.
// M,N multiples of 128; K multiple of 8. blockIdx.z = batch.
// ---------------------------------------------------------------------------
__global__ __launch_bounds__(256) void sgemm_k(
    const float* __restrict__ A, const float* __restrict__ Bsrc,
    float* __restrict__ Csrc, int M, int N, int K,
    const float* __restrict__ gamma, const float* __restrict__ beta,
    const float* __restrict__ mean,  const float* __restrict__ var)
{
    const float* Bm = Bsrc + (size_t)blockIdx.z * K * N;
    float*       Cm = Csrc + (size_t)blockIdx.z * M * N;

    __shared__ float As[8][128];
    __shared__ float Bs[8][128];

    const int tid = threadIdx.x;
    const int tx = tid & 15;        // 16 col groups of 8
    const int ty = tid >> 4;        // 16 row groups of 8

    const float* Ab = A  + (size_t)blockIdx.y * 128 * K;
    const float* Bb = Bm + (size_t)blockIdx.x * 128;

    float acc[8][8];
#pragma unroll
    for (int i = 0; i < 8; i++)
#pragma unroll
        for (int j = 0; j < 8; j++) acc[i][j] = 0.f;

    for (int k0 = 0; k0 < K; k0 += 8) {
        // Load A tile 128x8 (transposed into smem). Each thread: one float4.
        {
            int idx = tid * 4;
            int m  = idx >> 3;
            int kk = idx & 7;       // 0 or 4
            float4 v = *reinterpret_cast<const float4*>(Ab + (size_t)m * K + k0 + kk);
            As[kk + 0][m] = v.x; As[kk + 1][m] = v.y;
            As[kk + 2][m] = v.z; As[kk + 3][m] = v.w;
        }
        // Load B tile 8x128. Each thread: one float4.
        {
            int idx = tid * 4;
            int kk = idx >> 7;
            int n  = idx & 127;
            float4 v = *reinterpret_cast<const float4*>(Bb + (size_t)(k0 + kk) * N + n);
            *reinterpret_cast<float4*>(&Bs[kk][n]) = v;
        }
        __syncthreads();

#pragma unroll
        for (int kk = 0; kk < 8; kk++) {
            float ar[8], br[8];
#pragma unroll
            for (int i = 0; i < 8; i++) ar[i] = As[kk][ty * 8 + i];
#pragma unroll
            for (int j = 0; j < 8; j++) br[j] = Bs[kk][tx * 8 + j];
#pragma unroll
            for (int i = 0; i < 8; i++)
#pragma unroll
                for (int j = 0; j < 8; j++) acc[i][j] += ar[i] * br[j];
        }
        __syncthreads();
    }

#pragma unroll
    for (int i = 0; i < 8; i++) {
        int m = blockIdx.y * 128 + ty * 8 + i;
        float sc = 1.f, bi = 0.f;
        if (gamma) {
            float inv = gamma[m] * rsqrtf(var[m] + 1e-5f);
            sc = inv;
            bi = beta[m] - mean[m] * inv;
        }
        float* crow = Cm + (size_t)m * N + blockIdx.x * 128 + tx * 8;
        float4 v0, v1;
        v0.x = acc[i][0] * sc + bi; v0.y = acc[i][1] * sc + bi;
        v0.z = acc[i][2] * sc + bi; v0.w = acc[i][3] * sc + bi;
        v1.x = acc[i][4] * sc + bi; v1.y = acc[i][5] * sc + bi;
        v1.z = acc[i][6] * sc + bi; v1.w = acc[i][7] * sc + bi;
        *reinterpret_cast<float4*>(crow + 0) = v0;
        *reinterpret_cast<float4*>(crow + 4) = v1;
    }
}

// ---------------------------------------------------------------------------
// Depthwise 5x5 conv, pad 2. Block = 16x16 pixels, grid.z = b*768 + c.
// ---------------------------------------------------------------------------
__global__ __launch_bounds__(256) void dwconv5x5_k(const float* __restrict__ w_dw)
{
    const int bc = blockIdx.z;              // b*768 + c
    const int c  = bc % C3;
    const float* ip = g_qkv + (size_t)bc * HWN;
    float*       op = g_dw  + (size_t)bc * HWN;

    __shared__ float tile[20][20];
    __shared__ float wk[25];

    const int tx = threadIdx.x & 15, ty = threadIdx.x >> 4;
    const int x0 = blockIdx.x * 16, y0 = blockIdx.y * 16;

    if (threadIdx.x < 25) wk[threadIdx.x] = w_dw[c * 25 + threadIdx.x];

    for (int i = threadIdx.x; i < 400; i += 256) {
        int yy = i / 20, xx = i % 20;
        int gy = y0 + yy - 2, gx = x0 + xx - 2;
        tile[yy][xx] = (gy >= 0 && gy < 64 && gx >= 0 && gx < 64)
                           ? ip[gy * 64 + gx] : 0.f;
    }
    __syncthreads();

    float s = 0.f;
#pragma unroll
    for (int ky = 0; ky < 5; ky++)
#pragma unroll
        for (int kx = 0; kx < 5; kx++)
            s += tile[ty + ky][tx + kx] * wk[ky * 5 + kx];

    op[(y0 + ty) * 64 + x0 + tx] = s;
}

// ---------------------------------------------------------------------------
// Grouped pointwise: 96 groups, 8 in -> 8 out. One thread per (b,g,hw).
// ---------------------------------------------------------------------------
__global__ __launch_bounds__(256) void grouped_pw_k(const float* __restrict__ w_pw)
{
    int idx = blockIdx.x * 256 + threadIdx.x;
    int hw = idx & (HWN - 1);
    int g  = (idx >> 12) % 96;
    int b  = idx / (HWN * 96);

    const float* ip = g_dw + ((size_t)b * C3 + g * 8) * HWN + hw;
    float*       op = g_pw + ((size_t)b * C3 + g * 8) * HWN + hw;

    float vi[8];
#pragma unroll
    for (int i = 0; i < 8; i++) vi[i] = ip[i * HWN];

    const float* wg = w_pw + g * 64;
#pragma unroll
    for (int o = 0; o < 8; o++) {
        float s = 0.f;
#pragma unroll
        for (int i = 0; i < 8; i++) s += vi[i] * wg[o * 8 + i];
        op[o * HWN] = s;
    }
}

// ---------------------------------------------------------------------------
// ReLU linear attention. One block per (b,head); 64 heads of dim 8.
// Head h channels live at [24h, 24h+24) of concat(qkv, pw); since 768 = 32*24,
// heads 0..31 read g_qkv, heads 32..63 read g_pw.
// Pass 1: kv[d][e] = sum_n relu(k_nd) * v_ne (v has appended ones column).
// Pass 2: out[n][e] = sum_d relu(q_nd) kv[d][e]; emit out[:8]/(out[8]+eps).
// ---------------------------------------------------------------------------
__global__ __launch_bounds__(256) void litemla_att_k()
{
    const int bh = blockIdx.x;
    const int h = bh & 63;
    const int b = bh >> 6;

    const float* src = (h < 32)
        ? g_qkv + ((size_t)b * C3 + h * 24) * HWN
        : g_pw  + ((size_t)b * C3 + (h - 32) * 24) * HWN;

    float acc[72];
#pragma unroll
    for (int i = 0; i < 72; i++) acc[i] = 0.f;

    for (int hw = threadIdx.x; hw < HWN; hw += 256) {
        float kv_[8], vv[8];
#pragma unroll
        for (int d = 0; d < 8; d++) kv_[d] = fmaxf(src[(8 + d) * HWN + hw], 0.f);
#pragma unroll
        for (int e = 0; e < 8; e++) vv[e] = src[(16 + e) * HWN + hw];
#pragma unroll
        for (int d = 0; d < 8; d++) {
#pragma unroll
            for (int e = 0; e < 8; e++) acc[d * 9 + e] += kv_[d] * vv[e];
            acc[d * 9 + 8] += kv_[d];
        }
    }

    // Block reduction of 72 values.
    __shared__ float red[8][72];
    __shared__ float kvmat[72];
    const int lane = threadIdx.x & 31, warp = threadIdx.x >> 5;
#pragma unroll
    for (int i = 0; i < 72; i++) {
        float v = acc[i];
#pragma unroll
        for (int o = 16; o > 0; o >>= 1) v += __shfl_down_sync(0xffffffffu, v, o);
        if (lane == 0) red[warp][i] = v;
    }
    __syncthreads();
    if (threadIdx.x < 72) {
        float s = 0.f;
#pragma unroll
        for (int w2 = 0; w2 < 8; w2++) s += red[w2][threadIdx.x];
        kvmat[threadIdx.x] = s;
    }
    __syncthreads();

    float* dst = g_att + ((size_t)b * CATT + h * 8) * HWN;
    for (int hw = threadIdx.x; hw < HWN; hw += 256) {
        float q[8];
#pragma unroll
        for (int d = 0; d < 8; d++) q[d] = fmaxf(src[d * HWN + hw], 0.f);
        float o[9];
#pragma unroll
        for (int e = 0; e < 9; e++) {
            float s = 0.f;
#pragma unroll
            for (int d = 0; d < 8; d++) s += q[d] * kvmat[d * 9 + e];
            o[e] = s;
        }
        float inv = 1.f / (o[8] + 1e-15f);
#pragma unroll
        for (int e = 0; e < 8; e++) dst[e * HWN + hw] = o[e] * inv;
    }
}

// ---------------------------------------------------------------------------
extern "C" void kernel_launch(void* const* d_in, const int* in_sizes, int n_in,
                              void* d_out, int out_size)
{
    const float* x      = (const float*)d_in[0];
    const float* w_qkv  = (const float*)d_in[1];
    const float* w_dw   = (const float*)d_in[2];
    const float* w_pw   = (const float*)d_in[3];
    const float* w_proj = (const float*)d_in[4];
    const float* gm     = (const float*)d_in[5];
    const float* bt     = (const float*)d_in[6];
    const float* mn     = (const float*)d_in[7];
    const float* vr     = (const float*)d_in[8];
    float* out = (float*)d_out;

    float *qkv, *att;
    cudaGetSymbolAddress((void**)&qkv, g_qkv);
    cudaGetSymbolAddress((void**)&att, g_att);

    dim3 blk(256);

    // 1) qkv = w_qkv(768x256) @ x[b](256x4096)
    sgemm_k<<<dim3(32, 6, B_), blk>>>(w_qkv, x, qkv, 768, HWN, 256,
                                      nullptr, nullptr, nullptr, nullptr);
    // 2) depthwise 5x5
    dwconv5x5_k<<<dim3(4, 4, B_ * C3), blk>>>(w_dw);
    // 3) grouped pointwise
    grouped_pw_k<<<(B_ * 96 * HWN) / 256, blk>>>(w_pw);
    // 4) relu linear attention
    litemla_att_k<<<B_ * 64, blk>>>();
    // 5) proj + BN: out[b] = w_proj(256x512) @ att[b](512x4096) * inv + bias
    sgemm_k<<<dim3(32, 2, B_), blk>>>(w_proj, att, out, 256, HWN, 512,
                                      gm, bt, mn, vr);
}

// round 3
// speedup vs baseline: 1.8182x; 1.8182x over previous
#include <cuda_runtime.h>
#include <cstdint>

#define B_   8
#define HWN  4096
#define C3   768
#define CATT 512

__device__ float g_qkv[B_ * C3 * HWN];
__device__ float g_pw [B_ * C3 * HWN];
__device__ float g_att[B_ * CATT * HWN];
__device__ float g_kv [B_ * 64 * 72];

// ---------------------------------------------------------------------------
// 3xTF32 mma.sync GEMM: C[z] = A(MxK) * B[z](KxN), optional BN epilogue.
// Block tile 128x64, K tile 8, 8 warps (4x2), warp tile 32x32, double buffer.
// Each operand split into hi (tf32) + lo (tf32 of residual); accumulate
// hi*hi + hi*lo + lo*hi -> fp32-class accuracy on tensor cores.
// ---------------------------------------------------------------------------
#define TM 128
#define TN 64
#define TK 8
#define ASTR 12   // padded A smem row stride (floats) - conflict-free frag reads
#define BSTR 72   // padded B smem row stride - conflict-free frag reads

__device__ __forceinline__ uint32_t f2tf(float f) {
    uint32_t r;
    asm("cvt.rna.tf32.f32 %0, %1;" : "=r"(r) : "f"(f));
    return r;
}

__global__ __launch_bounds__(256) void gemm_3xtf32(
    const float* __restrict__ A, const float* __restrict__ Bsrc,
    float* __restrict__ Csrc, int M, int N, int K,
    const float* __restrict__ gamma, const float* __restrict__ beta,
    const float* __restrict__ mean,  const float* __restrict__ var)
{
    const float* Bm = Bsrc + (size_t)blockIdx.z * K * N;
    float*       Cm = Csrc + (size_t)blockIdx.z * M * N;

    // [buffer][part: 0=hi 1=lo]
    __shared__ uint32_t As[2][2][TM * ASTR];
    __shared__ uint32_t Bs[2][2][TK * BSTR];

    const int tid = threadIdx.x, lane = tid & 31, warp = tid >> 5;
    const int wm = warp >> 1, wn = warp & 1;      // 4 (m) x 2 (n) warps
    const int mbase = wm * 32, nbase = wn * 32;
    const int gr = lane >> 2, gc = lane & 3;

    const float* Ab = A  + (size_t)blockIdx.y * TM * K;
    const float* Bb = Bm + blockIdx.x * TN;

    float acc[2][4][4];
#pragma unroll
    for (int mt = 0; mt < 2; mt++)
#pragma unroll
        for (int nt = 0; nt < 4; nt++)
#pragma unroll
            for (int i = 0; i < 4; i++) acc[mt][nt][i] = 0.f;

    auto loadA = [&](int buf, int k0) {
        // 128 x 8 floats = 1024; 256 threads x float4
        int m = tid >> 1, k4 = (tid & 1) * 4;
        float4 v = *reinterpret_cast<const float4*>(Ab + (size_t)m * K + k0 + k4);
        uint32_t hx = f2tf(v.x), hy = f2tf(v.y), hz = f2tf(v.z), hw = f2tf(v.w);
        uint32_t* ph = &As[buf][0][m * ASTR + k4];
        uint32_t* pl = &As[buf][1][m * ASTR + k4];
        ph[0] = hx; ph[1] = hy; ph[2] = hz; ph[3] = hw;
        pl[0] = f2tf(v.x - __uint_as_float(hx));
        pl[1] = f2tf(v.y - __uint_as_float(hy));
        pl[2] = f2tf(v.z - __uint_as_float(hz));
        pl[3] = f2tf(v.w - __uint_as_float(hw));
    };
    auto loadB = [&](int buf, int k0) {
        // 8 x 64 floats = 512; 256 threads x float2
        int k = tid >> 5, n2 = (tid & 31) * 2;
        float2 v = *reinterpret_cast<const float2*>(Bb + (size_t)(k0 + k) * N + n2);
        uint32_t hx = f2tf(v.x), hy = f2tf(v.y);
        uint32_t* ph = &Bs[buf][0][k * BSTR + n2];
        uint32_t* pl = &Bs[buf][1][k * BSTR + n2];
        ph[0] = hx; ph[1] = hy;
        pl[0] = f2tf(v.x - __uint_as_float(hx));
        pl[1] = f2tf(v.y - __uint_as_float(hy));
    };

    loadA(0, 0); loadB(0, 0);
    __syncthreads();

    const int nk = K / TK;
    for (int kt = 0; kt < nk; kt++) {
        int cur = kt & 1, nxt = cur ^ 1;
        if (kt + 1 < nk) { loadA(nxt, (kt + 1) * TK); loadB(nxt, (kt + 1) * TK); }

        uint32_t ah[2][4], al[2][4], bh[4][2], bl[4][2];
#pragma unroll
        for (int mt = 0; mt < 2; mt++) {
            int m0 = mbase + mt * 16 + gr;
            ah[mt][0] = As[cur][0][(m0    ) * ASTR + gc    ];
            ah[mt][1] = As[cur][0][(m0 + 8) * ASTR + gc    ];
            ah[mt][2] = As[cur][0][(m0    ) * ASTR + gc + 4];
            ah[mt][3] = As[cur][0][(m0 + 8) * ASTR + gc + 4];
            al[mt][0] = As[cur][1][(m0    ) * ASTR + gc    ];
            al[mt][1] = As[cur][1][(m0 + 8) * ASTR + gc    ];
            al[mt][2] = As[cur][1][(m0    ) * ASTR + gc + 4];
            al[mt][3] = As[cur][1][(m0 + 8) * ASTR + gc + 4];
        }
#pragma unroll
        for (int nt = 0; nt < 4; nt++) {
            int n0 = nbase + nt * 8 + gr;
            bh[nt][0] = Bs[cur][0][(gc    ) * BSTR + n0];
            bh[nt][1] = Bs[cur][0][(gc + 4) * BSTR + n0];
            bl[nt][0] = Bs[cur][1][(gc    ) * BSTR + n0];
            bl[nt][1] = Bs[cur][1][(gc + 4) * BSTR + n0];
        }

#define MMA(acc_, a_, b_)                                                     \
    asm volatile(                                                             \
        "mma.sync.aligned.m16n8k8.row.col.f32.tf32.tf32.f32 "                 \
        "{%0,%1,%2,%3}, {%4,%5,%6,%7}, {%8,%9}, {%0,%1,%2,%3};"               \
        : "+f"(acc_[0]), "+f"(acc_[1]), "+f"(acc_[2]), "+f"(acc_[3])          \
        : "r"(a_[0]), "r"(a_[1]), "r"(a_[2]), "r"(a_[3]),                     \
          "r"(b_[0]), "r"(b_[1]))

#pragma unroll
        for (int mt = 0; mt < 2; mt++)
#pragma unroll
            for (int nt = 0; nt < 4; nt++) {
                MMA(acc[mt][nt], ah[mt], bl[nt]);   // hi*lo
                MMA(acc[mt][nt], al[mt], bh[nt]);   // lo*hi
                MMA(acc[mt][nt], ah[mt], bh[nt]);   // hi*hi (last: biggest term)
            }
#undef MMA
        __syncthreads();
    }

    // Epilogue (optional BN)
#pragma unroll
    for (int mt = 0; mt < 2; mt++) {
        int r0 = blockIdx.y * TM + mbase + mt * 16 + gr;
        int r1 = r0 + 8;
        float sc0 = 1.f, bi0 = 0.f, sc1 = 1.f, bi1 = 0.f;
        if (gamma) {
            float i0 = gamma[r0] * rsqrtf(var[r0] + 1e-5f);
            float i1 = gamma[r1] * rsqrtf(var[r1] + 1e-5f);
            sc0 = i0; bi0 = beta[r0] - mean[r0] * i0;
            sc1 = i1; bi1 = beta[r1] - mean[r1] * i1;
        }
#pragma unroll
        for (int nt = 0; nt < 4; nt++) {
            int col = blockIdx.x * TN + nbase + nt * 8 + gc * 2;
            float2 v0 = make_float2(acc[mt][nt][0] * sc0 + bi0, acc[mt][nt][1] * sc0 + bi0);
            float2 v1 = make_float2(acc[mt][nt][2] * sc1 + bi1, acc[mt][nt][3] * sc1 + bi1);
            *reinterpret_cast<float2*>(Cm + (size_t)r0 * N + col) = v0;
            *reinterpret_cast<float2*>(Cm + (size_t)r1 * N + col) = v1;
        }
    }
}

// ---------------------------------------------------------------------------
// Fused depthwise 5x5 (pad 2) + grouped pointwise (96 groups, 8->8).
// ---------------------------------------------------------------------------
__global__ __launch_bounds__(256) void dwpw_k(const float* __restrict__ w_dw,
                                              const float* __restrict__ w_pw)
{
    const int bz = blockIdx.z;
    const int g = bz % 96, b = bz / 96;

    __shared__ float t[8][20][20];
    __shared__ float wd[8][25];
    __shared__ float wp[64];

    const int tx = threadIdx.x & 15, ty = threadIdx.x >> 4;
    const int x0 = blockIdx.x * 16, y0 = blockIdx.y * 16;

    const float* ip = g_qkv + ((size_t)b * C3 + g * 8) * HWN;

    if (threadIdx.x < 200) wd[threadIdx.x / 25][threadIdx.x % 25] = w_dw[g * 200 + threadIdx.x];
    if (threadIdx.x < 64)  wp[threadIdx.x] = w_pw[g * 64 + threadIdx.x];

    for (int i = threadIdx.x; i < 3200; i += 256) {
        int c = i / 400, r = i % 400;
        int yy = r / 20, xx = r % 20;
        int gy = y0 + yy - 2, gx = x0 + xx - 2;
        t[c][yy][xx] = ((unsigned)gy < 64u && (unsigned)gx < 64u)
                           ? ip[c * HWN + gy * 64 + gx] : 0.f;
    }
    __syncthreads();

    float dv[8];
#pragma unroll
    for (int c = 0; c < 8; c++) {
        float s = 0.f;
#pragma unroll
        for (int ky = 0; ky < 5; ky++)
#pragma unroll
            for (int kx = 0; kx < 5; kx++)
                s += t[c][ty + ky][tx + kx] * wd[c][ky * 5 + kx];
        dv[c] = s;
    }

    float* op = g_pw + ((size_t)b * C3 + g * 8) * HWN + (y0 + ty) * 64 + x0 + tx;
#pragma unroll
    for (int o = 0; o < 8; o++) {
        float s = 0.f;
#pragma unroll
        for (int i = 0; i < 8; i++) s += dv[i] * wp[o * 8 + i];
        op[o * HWN] = s;
    }
}

// ---------------------------------------------------------------------------
// Attention pass 1: kv[d][e] partial sums per (b,h), atomicAdd into g_kv.
// ---------------------------------------------------------------------------
__global__ __launch_bounds__(256) void att1_k()
{
    const int bh = blockIdx.x;
    const int h = bh & 63, b = bh >> 6;

    const float* src = (h < 32)
        ? g_qkv + ((size_t)b * C3 + h * 24) * HWN
        : g_pw  + ((size_t)b * C3 + (h - 32) * 24) * HWN;

    float acc[72];
#pragma unroll
    for (int i = 0; i < 72; i++) acc[i] = 0.f;

    const int base = blockIdx.y * 1024;
#pragma unroll
    for (int it = 0; it < 4; it++) {
        int hw = base + it * 256 + threadIdx.x;
        float kk[8], vv[8];
#pragma unroll
        for (int d = 0; d < 8; d++) kk[d] = fmaxf(src[(8 + d) * HWN + hw], 0.f);
#pragma unroll
        for (int e = 0; e < 8; e++) vv[e] = src[(16 + e) * HWN + hw];
#pragma unroll
        for (int d = 0; d < 8; d++) {
#pragma unroll
            for (int e = 0; e < 8; e++) acc[d * 9 + e] += kk[d] * vv[e];
            acc[d * 9 + 8] += kk[d];
        }
    }

    __shared__ float red[8][72];
    const int lane = threadIdx.x & 31, warp = threadIdx.x >> 5;
#pragma unroll
    for (int i = 0; i < 72; i++) {
        float v = acc[i];
#pragma unroll
        for (int o = 16; o > 0; o >>= 1) v += __shfl_down_sync(0xffffffffu, v, o);
        if (lane == 0) red[warp][i] = v;
    }
    __syncthreads();
    if (threadIdx.x < 72) {
        float s = 0.f;
#pragma unroll
        for (int w = 0; w < 8; w++) s += red[w][threadIdx.x];
        atomicAdd(&g_kv[bh * 72 + threadIdx.x], s);
    }
}

// ---------------------------------------------------------------------------
// Attention pass 2: out = relu(q) @ kv, normalize by last column.
// ---------------------------------------------------------------------------
__global__ __launch_bounds__(256) void att2_k()
{
    const int bh = blockIdx.x;
    const int h = bh & 63, b = bh >> 6;

    const float* src = (h < 32)
        ? g_qkv + ((size_t)b * C3 + h * 24) * HWN
        : g_pw  + ((size_t)b * C3 + (h - 32) * 24) * HWN;

    __shared__ float kvm[72];
    if (threadIdx.x < 72) kvm[threadIdx.x] = g_kv[bh * 72 + threadIdx.x];
    __syncthreads();

    float* dst = g_att + ((size_t)b * CATT + h * 8) * HWN;
    const int base = blockIdx.y * 1024;
#pragma unroll
    for (int it = 0; it < 4; it++) {
        int hw = base + it * 256 + threadIdx.x;
        float q[8];
#pragma unroll
        for (int d = 0; d < 8; d++) q[d] = fmaxf(src[d * HWN + hw], 0.f);
        float o[9];
#pragma unroll
        for (int e = 0; e < 9; e++) {
            float s = 0.f;
#pragma unroll
            for (int d = 0; d < 8; d++) s += q[d] * kvm[d * 9 + e];
            o[e] = s;
        }
        float inv = 1.f / (o[8] + 1e-15f);
#pragma unroll
        for (int e = 0; e < 8; e++) dst[e * HWN + hw] = o[e] * inv;
    }
}

// ---------------------------------------------------------------------------
extern "C" void kernel_launch(void* const* d_in, const int* in_sizes, int n_in,
                              void* d_out, int out_size)
{
    const float* x      = (const float*)d_in[0];
    const float* w_qkv  = (const float*)d_in[1];
    const float* w_dw   = (const float*)d_in[2];
    const float* w_pw   = (const float*)d_in[3];
    const float* w_proj = (const float*)d_in[4];
    const float* gm     = (const float*)d_in[5];
    const float* bt     = (const float*)d_in[6];
    const float* mn     = (const float*)d_in[7];
    const float* vr     = (const float*)d_in[8];
    float* out = (float*)d_out;

    float *qkv, *att, *kv;
    cudaGetSymbolAddress((void**)&qkv, g_qkv);
    cudaGetSymbolAddress((void**)&att, g_att);
    cudaGetSymbolAddress((void**)&kv,  g_kv);

    dim3 blk(256);

    // 1) qkv = w_qkv(768x256) @ x[b](256x4096)
    gemm_3xtf32<<<dim3(HWN / TN, 768 / TM, B_), blk>>>(w_qkv, x, qkv, 768, HWN, 256,
                                                       nullptr, nullptr, nullptr, nullptr);
    // 2) fused dw 5x5 + grouped pw
    dwpw_k<<<dim3(4, 4, B_ * 96), blk>>>(w_dw, w_pw);
    // 3) attention
    cudaMemsetAsync(kv, 0, B_ * 64 * 72 * sizeof(float));
    att1_k<<<dim3(B_ * 64, 4), blk>>>();
    att2_k<<<dim3(B_ * 64, 4), blk>>>();
    // 4) proj + BN
    gemm_3xtf32<<<dim3(HWN / TN, 256 / TM, B_), blk>>>(w_proj, att, out, 256, HWN, 512,
                                                       gm, bt, mn, vr);
}

// round 4
// speedup vs baseline: 2.1260x; 1.1693x over previous
#include <cuda_runtime.h>
#include <cuda_bf16.h>
#include <cstdint>

#define B_   8
#define HWN  4096
#define C3   768
#define CATT 512

__device__ float g_qkv[B_ * C3 * HWN];
__device__ float g_pw [B_ * C3 * HWN];
__device__ float g_att[B_ * CATT * HWN];
__device__ float g_kv [B_ * 64 * 72];

// ---------------------------------------------------------------------------
// 3xBF16 split mma.sync GEMM (m16n8k16): C[z] = A(MxK)*B[z](KxN), opt BN.
// Block tile 128x128, K tile 16, 8 warps (2m x 4n), warp tile 64x32.
// x = hi + lo (both bf16); accumulate hi*hi + hi*lo + lo*hi in fp32.
// ---------------------------------------------------------------------------
#define TM 128
#define TN 128
#define TK 16
#define ASTR 12    // A smem row stride in u32 (8 k-pairs + pad) - conflict-free
#define BSTR 136   // B smem row stride in u32 (128 n + pad) - conflict-free

__device__ __forceinline__ uint32_t pk2(float e, float o) {
    __nv_bfloat162 t = __floats2bfloat162_rn(e, o);   // .x = e (low), .y = o (high)
    return *reinterpret_cast<uint32_t*>(&t);
}
__device__ __forceinline__ float bf_hi(float x, float& res) {
    __nv_bfloat16 h = __float2bfloat16_rn(x);
    float hf = __bfloat162float(h);
    res = x - hf;
    return hf;
}

__global__ __launch_bounds__(256, 1) void gemm_3xbf16(
    const float* __restrict__ A, const float* __restrict__ Bsrc,
    float* __restrict__ Csrc, int M, int N, int K,
    const float* __restrict__ gamma, const float* __restrict__ beta,
    const float* __restrict__ mean,  const float* __restrict__ var)
{
    const float* Bm = Bsrc + (size_t)blockIdx.z * K * N;
    float*       Cm = Csrc + (size_t)blockIdx.z * M * N;

    __shared__ uint32_t As[2][2][TM * ASTR];     // [buf][hi/lo][m][k2]
    __shared__ uint32_t Bs[2][2][(TK / 2) * BSTR]; // [buf][hi/lo][k2][n]

    const int tid = threadIdx.x, lane = tid & 31, warp = tid >> 5;
    const int wm = warp >> 2, wn = warp & 3;      // 2 (m) x 4 (n)
    const int gr = lane >> 2, gc = lane & 3;

    const float* Ab = A  + (size_t)blockIdx.y * TM * K;
    const float* Bb = Bm + blockIdx.x * TN;

    float acc[4][4][4];                            // [mt][nt][4]
#pragma unroll
    for (int mt = 0; mt < 4; mt++)
#pragma unroll
        for (int nt = 0; nt < 4; nt++)
#pragma unroll
            for (int i = 0; i < 4; i++) acc[mt][nt][i] = 0.f;

    auto loadA = [&](int buf, int k0) {
        // 128 rows x 16 k: thread -> (m = tid>>1, k8 = (tid&1)*8)
        int m = tid >> 1, k8 = (tid & 1) * 8;
        const float* p = Ab + (size_t)m * K + k0 + k8;
        float4 v0 = *reinterpret_cast<const float4*>(p);
        float4 v1 = *reinterpret_cast<const float4*>(p + 4);
        float f[8] = {v0.x, v0.y, v0.z, v0.w, v1.x, v1.y, v1.z, v1.w};
        uint32_t hp[4], lp[4];
#pragma unroll
        for (int i = 0; i < 4; i++) {
            float r0, r1;
            float h0 = bf_hi(f[2 * i], r0), h1 = bf_hi(f[2 * i + 1], r1);
            hp[i] = pk2(h0, h1);
            lp[i] = pk2(r0, r1);
        }
        int o = m * ASTR + (k8 >> 1);
        *reinterpret_cast<uint4*>(&As[buf][0][o]) = *reinterpret_cast<uint4*>(hp);
        *reinterpret_cast<uint4*>(&As[buf][1][o]) = *reinterpret_cast<uint4*>(lp);
    };
    auto loadB = [&](int buf, int k0) {
        // 16 rows x 128 n: thread -> (k2 = tid>>5, n4 = (tid&31)*4)
        int k2 = tid >> 5, n4 = (lane) * 4;
        const float* p0 = Bb + (size_t)(k0 + 2 * k2) * N + n4;
        const float* p1 = p0 + N;
        float4 u = *reinterpret_cast<const float4*>(p0);
        float4 w = *reinterpret_cast<const float4*>(p1);
        float ue[4] = {u.x, u.y, u.z, u.w}, wo[4] = {w.x, w.y, w.z, w.w};
        uint32_t hp[4], lp[4];
#pragma unroll
        for (int j = 0; j < 4; j++) {
            float r0, r1;
            float h0 = bf_hi(ue[j], r0), h1 = bf_hi(wo[j], r1);
            hp[j] = pk2(h0, h1);                  // low = even k, high = odd k
            lp[j] = pk2(r0, r1);
        }
        int o = k2 * BSTR + n4;
        *reinterpret_cast<uint4*>(&Bs[buf][0][o]) = *reinterpret_cast<uint4*>(hp);
        *reinterpret_cast<uint4*>(&Bs[buf][1][o]) = *reinterpret_cast<uint4*>(lp);
    };

    loadA(0, 0); loadB(0, 0);
    __syncthreads();

#define MMA(acc_, a_, b_)                                                     \
    asm volatile(                                                             \
        "mma.sync.aligned.m16n8k16.row.col.f32.bf16.bf16.f32 "                \
        "{%0,%1,%2,%3}, {%4,%5,%6,%7}, {%8,%9}, {%0,%1,%2,%3};"               \
        : "+f"(acc_[0]), "+f"(acc_[1]), "+f"(acc_[2]), "+f"(acc_[3])          \
        : "r"(a_[0]), "r"(a_[1]), "r"(a_[2]), "r"(a_[3]),                     \
          "r"(b_[0]), "r"(b_[1]))

    const int nk = K / TK;
    for (int kt = 0; kt < nk; kt++) {
        int cur = kt & 1, nxt = cur ^ 1;
        if (kt + 1 < nk) { loadA(nxt, (kt + 1) * TK); loadB(nxt, (kt + 1) * TK); }

        uint32_t bh[4][2], bl[4][2];
#pragma unroll
        for (int nt = 0; nt < 4; nt++) {
            int n0 = wn * 32 + nt * 8 + gr;
            bh[nt][0] = Bs[cur][0][(gc    ) * BSTR + n0];
            bh[nt][1] = Bs[cur][0][(gc + 4) * BSTR + n0];
            bl[nt][0] = Bs[cur][1][(gc    ) * BSTR + n0];
            bl[nt][1] = Bs[cur][1][(gc + 4) * BSTR + n0];
        }
#pragma unroll
        for (int mt = 0; mt < 4; mt++) {
            int m0 = wm * 64 + mt * 16 + gr;
            uint32_t ah[4], al[4];
            ah[0] = As[cur][0][(m0    ) * ASTR + gc    ];
            ah[1] = As[cur][0][(m0 + 8) * ASTR + gc    ];
            ah[2] = As[cur][0][(m0    ) * ASTR + gc + 4];
            ah[3] = As[cur][0][(m0 + 8) * ASTR + gc + 4];
            al[0] = As[cur][1][(m0    ) * ASTR + gc    ];
            al[1] = As[cur][1][(m0 + 8) * ASTR + gc    ];
            al[2] = As[cur][1][(m0    ) * ASTR + gc + 4];
            al[3] = As[cur][1][(m0 + 8) * ASTR + gc + 4];
#pragma unroll
            for (int nt = 0; nt < 4; nt++) {
                MMA(acc[mt][nt], ah, bl[nt]);   // hi*lo
                MMA(acc[mt][nt], al, bh[nt]);   // lo*hi
                MMA(acc[mt][nt], ah, bh[nt]);   // hi*hi
            }
        }
        __syncthreads();
    }
#undef MMA

    // Epilogue (optional BN)
#pragma unroll
    for (int mt = 0; mt < 4; mt++) {
        int r0 = blockIdx.y * TM + wm * 64 + mt * 16 + gr;
        int r1 = r0 + 8;
        float sc0 = 1.f, bi0 = 0.f, sc1 = 1.f, bi1 = 0.f;
        if (gamma) {
            float i0 = gamma[r0] * rsqrtf(var[r0] + 1e-5f);
            float i1 = gamma[r1] * rsqrtf(var[r1] + 1e-5f);
            sc0 = i0; bi0 = beta[r0] - mean[r0] * i0;
            sc1 = i1; bi1 = beta[r1] - mean[r1] * i1;
        }
#pragma unroll
        for (int nt = 0; nt < 4; nt++) {
            int col = blockIdx.x * TN + wn * 32 + nt * 8 + gc * 2;
            float2 v0 = make_float2(acc[mt][nt][0] * sc0 + bi0, acc[mt][nt][1] * sc0 + bi0);
            float2 v1 = make_float2(acc[mt][nt][2] * sc1 + bi1, acc[mt][nt][3] * sc1 + bi1);
            *reinterpret_cast<float2*>(Cm + (size_t)r0 * N + col) = v0;
            *reinterpret_cast<float2*>(Cm + (size_t)r1 * N + col) = v1;
        }
    }
}

// ---------------------------------------------------------------------------
// Fused depthwise 5x5 (pad 2) + grouped pointwise (96 groups, 8->8).
// ---------------------------------------------------------------------------
__global__ __launch_bounds__(256) void dwpw_k(const float* __restrict__ w_dw,
                                              const float* __restrict__ w_pw)
{
    const int bz = blockIdx.z;
    const int g = bz % 96, b = bz / 96;

    __shared__ float t[8][20][20];
    __shared__ float wd[8][25];
    __shared__ float wp[64];

    const int tx = threadIdx.x & 15, ty = threadIdx.x >> 4;
    const int x0 = blockIdx.x * 16, y0 = blockIdx.y * 16;

    const float* ip = g_qkv + ((size_t)b * C3 + g * 8) * HWN;

    if (threadIdx.x < 200) wd[threadIdx.x / 25][threadIdx.x % 25] = w_dw[g * 200 + threadIdx.x];
    if (threadIdx.x < 64)  wp[threadIdx.x] = w_pw[g * 64 + threadIdx.x];

    for (int i = threadIdx.x; i < 3200; i += 256) {
        int c = i / 400, r = i % 400;
        int yy = r / 20, xx = r % 20;
        int gy = y0 + yy - 2, gx = x0 + xx - 2;
        t[c][yy][xx] = ((unsigned)gy < 64u && (unsigned)gx < 64u)
                           ? ip[c * HWN + gy * 64 + gx] : 0.f;
    }
    __syncthreads();

    float dv[8];
#pragma unroll
    for (int c = 0; c < 8; c++) {
        float s = 0.f;
#pragma unroll
        for (int ky = 0; ky < 5; ky++)
#pragma unroll
            for (int kx = 0; kx < 5; kx++)
                s += t[c][ty + ky][tx + kx] * wd[c][ky * 5 + kx];
        dv[c] = s;
    }

    float* op = g_pw + ((size_t)b * C3 + g * 8) * HWN + (y0 + ty) * 64 + x0 + tx;
#pragma unroll
    for (int o = 0; o < 8; o++) {
        float s = 0.f;
#pragma unroll
        for (int i = 0; i < 8; i++) s += dv[i] * wp[o * 8 + i];
        op[o * HWN] = s;
    }
}

// ---------------------------------------------------------------------------
// Attention pass 1: kv[d][e] partial sums per (b,h), atomicAdd into g_kv.
// ---------------------------------------------------------------------------
__global__ __launch_bounds__(256) void att1_k()
{
    const int bh = blockIdx.x;
    const int h = bh & 63, b = bh >> 6;

    const float* src = (h < 32)
        ? g_qkv + ((size_t)b * C3 + h * 24) * HWN
        : g_pw  + ((size_t)b * C3 + (h - 32) * 24) * HWN;

    float acc[72];
#pragma unroll
    for (int i = 0; i < 72; i++) acc[i] = 0.f;

    const int base = blockIdx.y * 1024;
#pragma unroll
    for (int it = 0; it < 4; it++) {
        int hw = base + it * 256 + threadIdx.x;
        float kk[8], vv[8];
#pragma unroll
        for (int d = 0; d < 8; d++) kk[d] = fmaxf(src[(8 + d) * HWN + hw], 0.f);
#pragma unroll
        for (int e = 0; e < 8; e++) vv[e] = src[(16 + e) * HWN + hw];
#pragma unroll
        for (int d = 0; d < 8; d++) {
#pragma unroll
            for (int e = 0; e < 8; e++) acc[d * 9 + e] += kk[d] * vv[e];
            acc[d * 9 + 8] += kk[d];
        }
    }

    __shared__ float red[8][72];
    const int lane = threadIdx.x & 31, warp = threadIdx.x >> 5;
#pragma unroll
    for (int i = 0; i < 72; i++) {
        float v = acc[i];
#pragma unroll
        for (int o = 16; o > 0; o >>= 1) v += __shfl_down_sync(0xffffffffu, v, o);
        if (lane == 0) red[warp][i] = v;
    }
    __syncthreads();
    if (threadIdx.x < 72) {
        float s = 0.f;
#pragma unroll
        for (int w = 0; w < 8; w++) s += red[w][threadIdx.x];
        atomicAdd(&g_kv[bh * 72 + threadIdx.x], s);
    }
}

// ---------------------------------------------------------------------------
// Attention pass 2: out = relu(q) @ kv, normalize by last column.
// ---------------------------------------------------------------------------
__global__ __launch_bounds__(256) void att2_k()
{
    const int bh = blockIdx.x;
    const int h = bh & 63, b = bh >> 6;

    const float* src = (h < 32)
        ? g_qkv + ((size_t)b * C3 + h * 24) * HWN
        : g_pw  + ((size_t)b * C3 + (h - 32) * 24) * HWN;

    __shared__ float kvm[72];
    if (threadIdx.x < 72) kvm[threadIdx.x] = g_kv[bh * 72 + threadIdx.x];
    __syncthreads();

    float* dst = g_att + ((size_t)b * CATT + h * 8) * HWN;
    const int base = blockIdx.y * 1024;
#pragma unroll
    for (int it = 0; it < 4; it++) {
        int hw = base + it * 256 + threadIdx.x;
        float q[8];
#pragma unroll
        for (int d = 0; d < 8; d++) q[d] = fmaxf(src[d * HWN + hw], 0.f);
        float o[9];
#pragma unroll
        for (int e = 0; e < 9; e++) {
            float s = 0.f;
#pragma unroll
            for (int d = 0; d < 8; d++) s += q[d] * kvm[d * 9 + e];
            o[e] = s;
        }
        float inv = 1.f / (o[8] + 1e-15f);
#pragma unroll
        for (int e = 0; e < 8; e++) dst[e * HWN + hw] = o[e] * inv;
    }
}

// ---------------------------------------------------------------------------
extern "C" void kernel_launch(void* const* d_in, const int* in_sizes, int n_in,
                              void* d_out, int out_size)
{
    const float* x      = (const float*)d_in[0];
    const float* w_qkv  = (const float*)d_in[1];
    const float* w_dw   = (const float*)d_in[2];
    const float* w_pw   = (const float*)d_in[3];
    const float* w_proj = (const float*)d_in[4];
    const float* gm     = (const float*)d_in[5];
    const float* bt     = (const float*)d_in[6];
    const float* mn     = (const float*)d_in[7];
    const float* vr     = (const float*)d_in[8];
    float* out = (float*)d_out;

    float *qkv, *att, *kv;
    cudaGetSymbolAddress((void**)&qkv, g_qkv);
    cudaGetSymbolAddress((void**)&att, g_att);
    cudaGetSymbolAddress((void**)&kv,  g_kv);

    dim3 blk(256);

    // 1) qkv = w_qkv(768x256) @ x[b](256x4096)
    gemm_3xbf16<<<dim3(HWN / TN, 768 / TM, B_), blk>>>(w_qkv, x, qkv, 768, HWN, 256,
                                                       nullptr, nullptr, nullptr, nullptr);
    // 2) fused dw 5x5 + grouped pw
    dwpw_k<<<dim3(4, 4, B_ * 96), blk>>>(w_dw, w_pw);
    // 3) attention
    cudaMemsetAsync(kv, 0, B_ * 64 * 72 * sizeof(float));
    att1_k<<<dim3(B_ * 64, 4), blk>>>();
    att2_k<<<dim3(B_ * 64, 4), blk>>>();
    // 4) proj + BN
    gemm_3xbf16<<<dim3(HWN / TN, 256 / TM, B_), blk>>>(w_proj, att, out, 256, HWN, 512,
                                                       gm, bt, mn, vr);
}

// round 6
// speedup vs baseline: 2.7623x; 1.2993x over previous
#include <cuda_runtime.h>
#include <cuda_fp16.h>
#include <cstdint>

#define B_   8
#define HWN  4096
#define C3   768
#define CATT 512

// fp32 intermediates
__device__ float g_qkv[B_ * C3 * HWN];    // qkv (GEMM1 out)
__device__ float g_pw [B_ * C3 * HWN];    // dw+pw out
__device__ float g_kv [B_ * 64 * 72];

// fp16 split planes (GEMM operands)
__device__ __half g_xh [B_ * 256 * HWN];
__device__ __half g_xl [B_ * 256 * HWN];
__device__ __half g_ath[B_ * CATT * HWN];
__device__ __half g_atl[B_ * CATT * HWN];
__device__ __half g_wqh[768 * 256];
__device__ __half g_wql[768 * 256];
__device__ __half g_wph[256 * 512];
__device__ __half g_wpl[256 * 512];

// ===========================================================================
// helpers
// ===========================================================================
__device__ __forceinline__ uint32_t smem_u32(const void* p) {
    uint32_t a;
    asm("{ .reg .u64 t; cvta.to.shared.u64 t, %1; cvt.u32.u64 %0, t; }"
        : "=r"(a) : "l"(p));
    return a;
}
__device__ __forceinline__ void cpa16(uint32_t dst, const void* src) {
    asm volatile("cp.async.cg.shared.global [%0], [%1], 16;"
                 :: "r"(dst), "l"(src) : "memory");
}
#define CP_COMMIT() asm volatile("cp.async.commit_group;" ::: "memory")
#define CP_WAIT1()  asm volatile("cp.async.wait_group 1;" ::: "memory")

#define LDSM(r0,r1,r2,r3,a) \
    asm volatile("ldmatrix.sync.aligned.m8n8.x4.shared.b16 {%0,%1,%2,%3}, [%4];" \
        : "=r"(r0),"=r"(r1),"=r"(r2),"=r"(r3) : "r"(a))
#define LDSMT(r0,r1,r2,r3,a) \
    asm volatile("ldmatrix.sync.aligned.m8n8.x4.trans.shared.b16 {%0,%1,%2,%3}, [%4];" \
        : "=r"(r0),"=r"(r1),"=r"(r2),"=r"(r3) : "r"(a))
#define MMA(acc_, a_, b0_, b1_) \
    asm volatile("mma.sync.aligned.m16n8k16.row.col.f32.f16.f16.f32 " \
        "{%0,%1,%2,%3}, {%4,%5,%6,%7}, {%8,%9}, {%0,%1,%2,%3};" \
        : "+f"(acc_[0]), "+f"(acc_[1]), "+f"(acc_[2]), "+f"(acc_[3]) \
        : "r"(a_[0]), "r"(a_[1]), "r"(a_[2]), "r"(a_[3]), "r"(b0_), "r"(b1_))

// ===========================================================================
// split fp32 -> fp16 hi/lo planes. n4 = element count / 4.
// ===========================================================================
__global__ __launch_bounds__(256) void split_pair_k(
    const float* __restrict__ src, __half2* __restrict__ h2,
    __half2* __restrict__ l2, int n4)
{
    int i = blockIdx.x * 256 + threadIdx.x;
    if (i >= n4) return;
    float4 v = reinterpret_cast<const float4*>(src)[i];
    float f[4] = {v.x, v.y, v.z, v.w};
    __half hh[4], ll[4];
#pragma unroll
    for (int j = 0; j < 4; j++) {
        hh[j] = __float2half_rn(f[j]);
        ll[j] = __float2half_rn(f[j] - __half2float(hh[j]));
    }
    h2[2 * i]     = __halves2half2(hh[0], hh[1]);
    h2[2 * i + 1] = __halves2half2(hh[2], hh[3]);
    l2[2 * i]     = __halves2half2(ll[0], ll[1]);
    l2[2 * i + 1] = __halves2half2(ll[2], ll[3]);
}

// ===========================================================================
// fp16x2-split GEMM: C[z](MxN) = A(MxK) @ B[z](KxN), fp32 acc, 3 products
// (AhBh + AhBl + AlBh). Tiles 128x128x16, 8 warps (2m x 4n), 3-stage cp.async,
// ldmatrix fragments. Optional BN epilogue on rows.
// ===========================================================================
#define STAGES 3
#define AOFF_L 6144
#define BOFF_H 12288
#define BOFF_L 16640
#define STG_BYTES 20992
#define GEMM_DSMEM (STAGES * STG_BYTES)

__global__ __launch_bounds__(256, 2) void gemm_fp16x2(
    const __half* __restrict__ Ah, const __half* __restrict__ Al,
    const __half* __restrict__ Bh, const __half* __restrict__ Bl,
    float* __restrict__ Csrc, int M, int N, int K,
    const float* __restrict__ gamma, const float* __restrict__ beta,
    const float* __restrict__ mean,  const float* __restrict__ var)
{
    extern __shared__ char dsm[];
    const uint32_t sb = smem_u32(dsm);

    const int tid = threadIdx.x, lane = tid & 31, warp = tid >> 5;
    const int wm = warp >> 2, wn = warp & 3;
    const int gr = lane >> 2, gc = lane & 3;

    const size_t bz = (size_t)blockIdx.z * K * N;
    float* Cm = Csrc + (size_t)blockIdx.z * M * N;

    // cp.async source/dest mapping
    const int arow = tid >> 1, ach = tid & 1;
    const __half* aSrcH = Ah + (size_t)(blockIdx.y * 128 + arow) * K + ach * 8;
    const __half* aSrcL = Al + (size_t)(blockIdx.y * 128 + arow) * K + ach * 8;
    const int brow = tid >> 4, bch = tid & 15;
    const __half* bSrcH = Bh + bz + (size_t)brow * N + blockIdx.x * 128 + bch * 8;
    const __half* bSrcL = Bl + bz + (size_t)brow * N + blockIdx.x * 128 + bch * 8;
    const uint32_t aDst = arow * 48 + ach * 16;
    const uint32_t bDst = brow * 272 + bch * 16;

    auto issue = [&](int kt) {
        uint32_t st = sb + (kt % STAGES) * STG_BYTES;
        size_t ka = (size_t)kt * 16;
        cpa16(st + aDst,          aSrcH + ka);
        cpa16(st + AOFF_L + aDst, aSrcL + ka);
        cpa16(st + BOFF_H + bDst, bSrcH + ka * N);
        cpa16(st + BOFF_L + bDst, bSrcL + ka * N);
    };

    float acc[4][4][4];
#pragma unroll
    for (int mt = 0; mt < 4; mt++)
#pragma unroll
        for (int nt = 0; nt < 4; nt++)
#pragma unroll
            for (int i = 0; i < 4; i++) acc[mt][nt][i] = 0.f;

    const int nk = K / 16;
    issue(0); CP_COMMIT();
    issue(1); CP_COMMIT();

    // fragment address components
    const uint32_t bq = ((lane & 7) + 8 * ((lane >> 3) & 1)) * 272;
    const uint32_t aq = (lane & 15) * 48 + (lane >> 4) * 16;

    for (int kt = 0; kt < nk; kt++) {
        CP_WAIT1();
        __syncthreads();
        if (kt + 2 < nk) issue(kt + 2);
        CP_COMMIT();

        const uint32_t st = sb + (kt % STAGES) * STG_BYTES;

        uint32_t bfr[2][2][4];   // [plane][ng][reg]
#pragma unroll
        for (int ng = 0; ng < 2; ng++) {
            uint32_t nb = (wn * 32 + ng * 16 + 8 * (lane >> 4)) * 2;
            uint32_t adH = st + BOFF_H + bq + nb;
            uint32_t adL = st + BOFF_L + bq + nb;
            LDSMT(bfr[0][ng][0], bfr[0][ng][1], bfr[0][ng][2], bfr[0][ng][3], adH);
            LDSMT(bfr[1][ng][0], bfr[1][ng][1], bfr[1][ng][2], bfr[1][ng][3], adL);
        }
#pragma unroll
        for (int mt = 0; mt < 4; mt++) {
            uint32_t ma = st + (wm * 64 + mt * 16) * 48 + aq;
            uint32_t ah[4], al[4];
            LDSM(ah[0], ah[1], ah[2], ah[3], ma);
            LDSM(al[0], al[1], al[2], al[3], ma + AOFF_L);
#pragma unroll
            for (int ng = 0; ng < 2; ng++)
#pragma unroll
                for (int j = 0; j < 2; j++) {
                    int nt = 2 * ng + j;
                    MMA(acc[mt][nt], ah, bfr[1][ng][2 * j], bfr[1][ng][2 * j + 1]);
                    MMA(acc[mt][nt], al, bfr[0][ng][2 * j], bfr[0][ng][2 * j + 1]);
                    MMA(acc[mt][nt], ah, bfr[0][ng][2 * j], bfr[0][ng][2 * j + 1]);
                }
        }
    }

    // epilogue
#pragma unroll
    for (int mt = 0; mt < 4; mt++) {
        int r0 = blockIdx.y * 128 + wm * 64 + mt * 16 + gr;
        int r1 = r0 + 8;
        float sc0 = 1.f, bi0 = 0.f, sc1 = 1.f, bi1 = 0.f;
        if (gamma) {
            float i0 = gamma[r0] * rsqrtf(var[r0] + 1e-5f);
            float i1 = gamma[r1] * rsqrtf(var[r1] + 1e-5f);
            sc0 = i0; bi0 = beta[r0] - mean[r0] * i0;
            sc1 = i1; bi1 = beta[r1] - mean[r1] * i1;
        }
#pragma unroll
        for (int nt = 0; nt < 4; nt++) {
            int col = blockIdx.x * 128 + wn * 32 + nt * 8 + gc * 2;
            float2 v0 = make_float2(acc[mt][nt][0] * sc0 + bi0, acc[mt][nt][1] * sc0 + bi0);
            float2 v1 = make_float2(acc[mt][nt][2] * sc1 + bi1, acc[mt][nt][3] * sc1 + bi1);
            *reinterpret_cast<float2*>(Cm + (size_t)r0 * N + col) = v0;
            *reinterpret_cast<float2*>(Cm + (size_t)r1 * N + col) = v1;
        }
    }
}

// ===========================================================================
// Fused depthwise 5x5 (pad 2) + grouped pointwise (96 groups, 8->8).
// ===========================================================================
__global__ __launch_bounds__(256) void dwpw_k(const float* __restrict__ w_dw,
                                              const float* __restrict__ w_pw)
{
    const int bz = blockIdx.z;
    const int g = bz % 96, b = bz / 96;

    __shared__ float t[8][20][20];
    __shared__ float wd[8][25];
    __shared__ float wp[64];

    const int tx = threadIdx.x & 15, ty = threadIdx.x >> 4;
    const int x0 = blockIdx.x * 16, y0 = blockIdx.y * 16;

    const float* ip = g_qkv + ((size_t)b * C3 + g * 8) * HWN;

    if (threadIdx.x < 200) wd[threadIdx.x / 25][threadIdx.x % 25] = w_dw[g * 200 + threadIdx.x];
    if (threadIdx.x < 64)  wp[threadIdx.x] = w_pw[g * 64 + threadIdx.x];

    for (int i = threadIdx.x; i < 3200; i += 256) {
        int ch = i / 400, r2 = i % 400;
        int yy = r2 / 20, xx = r2 % 20;
        int gy = y0 + yy - 2, gx = x0 + xx - 2;
        t[ch][yy][xx] = ((unsigned)gy < 64u && (unsigned)gx < 64u)
                            ? ip[ch * HWN + gy * 64 + gx] : 0.f;
    }
    __syncthreads();

    float dv[8];
#pragma unroll
    for (int ch = 0; ch < 8; ch++) {
        float s = 0.f;
#pragma unroll
        for (int ky = 0; ky < 5; ky++)
#pragma unroll
            for (int kx = 0; kx < 5; kx++)
                s += t[ch][ty + ky][tx + kx] * wd[ch][ky * 5 + kx];
        dv[ch] = s;
    }

    float* op = g_pw + ((size_t)b * C3 + g * 8) * HWN + (y0 + ty) * 64 + x0 + tx;
#pragma unroll
    for (int o = 0; o < 8; o++) {
        float s = 0.f;
#pragma unroll
        for (int i = 0; i < 8; i++) s += dv[i] * wp[o * 8 + i];
        op[o * HWN] = s;
    }
}

// ===========================================================================
// Attention pass 1: kv[d][e] partial sums per (b,h), atomicAdd into g_kv.
// ===========================================================================
__global__ __launch_bounds__(256) void att1_k()
{
    const int bh = blockIdx.x;
    const int h = bh & 63, b = bh >> 6;

    const float* src = (h < 32)
        ? g_qkv + ((size_t)b * C3 + h * 24) * HWN
        : g_pw  + ((size_t)b * C3 + (h - 32) * 24) * HWN;

    float acc[72];
#pragma unroll
    for (int i = 0; i < 72; i++) acc[i] = 0.f;

    const int base = blockIdx.y * 1024;
#pragma unroll
    for (int it = 0; it < 4; it++) {
        int hw = base + it * 256 + threadIdx.x;
        float kk[8], vv[8];
#pragma unroll
        for (int d = 0; d < 8; d++) kk[d] = fmaxf(src[(8 + d) * HWN + hw], 0.f);
#pragma unroll
        for (int e = 0; e < 8; e++) vv[e] = src[(16 + e) * HWN + hw];
#pragma unroll
        for (int d = 0; d < 8; d++) {
#pragma unroll
            for (int e = 0; e < 8; e++) acc[d * 9 + e] += kk[d] * vv[e];
            acc[d * 9 + 8] += kk[d];
        }
    }

    __shared__ float red[8][72];
    const int lane = threadIdx.x & 31, warp = threadIdx.x >> 5;
#pragma unroll
    for (int i = 0; i < 72; i++) {
        float v = acc[i];
#pragma unroll
        for (int o = 16; o > 0; o >>= 1) v += __shfl_down_sync(0xffffffffu, v, o);
        if (lane == 0) red[warp][i] = v;
    }
    __syncthreads();
    if (threadIdx.x < 72) {
        float s = 0.f;
#pragma unroll
        for (int w = 0; w < 8; w++) s += red[w][threadIdx.x];
        atomicAdd(&g_kv[bh * 72 + threadIdx.x], s);
    }
}

// ===========================================================================
// Attention pass 2: out = relu(q) @ kv, normalize; write fp16 hi/lo planes.
// ===========================================================================
__global__ __launch_bounds__(256) void att2_k()
{
    const int bh = blockIdx.x;
    const int h = bh & 63, b = bh >> 6;

    const float* src = (h < 32)
        ? g_qkv + ((size_t)b * C3 + h * 24) * HWN
        : g_pw  + ((size_t)b * C3 + (h - 32) * 24) * HWN;

    __shared__ float kvm[72];
    if (threadIdx.x < 72) kvm[threadIdx.x] = g_kv[bh * 72 + threadIdx.x];
    __syncthreads();

    const size_t dbase = ((size_t)b * CATT + h * 8) * HWN;
    const int base = blockIdx.y * 1024;
#pragma unroll
    for (int it = 0; it < 4; it++) {
        int hw = base + it * 256 + threadIdx.x;
        float q[8];
#pragma unroll
        for (int d = 0; d < 8; d++) q[d] = fmaxf(src[d * HWN + hw], 0.f);
        float o[9];
#pragma unroll
        for (int e = 0; e < 9; e++) {
            float s = 0.f;
#pragma unroll
            for (int d = 0; d < 8; d++) s += q[d] * kvm[d * 9 + e];
            o[e] = s;
        }
        float inv = 1.f / (o[8] + 1e-15f);
#pragma unroll
        for (int e = 0; e < 8; e++) {
            float val = o[e] * inv;
            __half hh = __float2half_rn(val);
            g_ath[dbase + e * HWN + hw] = hh;
            g_atl[dbase + e * HWN + hw] = __float2half_rn(val - __half2float(hh));
        }
    }
}

// ===========================================================================
extern "C" void kernel_launch(void* const* d_in, const int* in_sizes, int n_in,
                              void* d_out, int out_size)
{
    const float* x      = (const float*)d_in[0];
    const float* w_qkv  = (const float*)d_in[1];
    const float* w_dw   = (const float*)d_in[2];
    const float* w_pw   = (const float*)d_in[3];
    const float* w_proj = (const float*)d_in[4];
    const float* gm     = (const float*)d_in[5];
    const float* bt     = (const float*)d_in[6];
    const float* mn     = (const float*)d_in[7];
    const float* vr     = (const float*)d_in[8];
    float* out = (float*)d_out;

    float *qkv, *kv;
    __half *xh, *xl, *ath, *atl, *wqh, *wql, *wph, *wpl;
    cudaGetSymbolAddress((void**)&qkv, g_qkv);
    cudaGetSymbolAddress((void**)&kv,  g_kv);
    cudaGetSymbolAddress((void**)&xh,  g_xh);
    cudaGetSymbolAddress((void**)&xl,  g_xl);
    cudaGetSymbolAddress((void**)&ath, g_ath);
    cudaGetSymbolAddress((void**)&atl, g_atl);
    cudaGetSymbolAddress((void**)&wqh, g_wqh);
    cudaGetSymbolAddress((void**)&wql, g_wql);
    cudaGetSymbolAddress((void**)&wph, g_wph);
    cudaGetSymbolAddress((void**)&wpl, g_wpl);

    cudaFuncSetAttribute(gemm_fp16x2, cudaFuncAttributeMaxDynamicSharedMemorySize,
                         GEMM_DSMEM);

    dim3 blk(256);

    // 0) split operands into fp16 hi/lo planes
    int nx4 = (B_ * 256 * HWN) / 4;
    split_pair_k<<<(nx4 + 255) / 256, blk>>>(x, (__half2*)xh, (__half2*)xl, nx4);
    int nq4 = (768 * 256) / 4;
    split_pair_k<<<(nq4 + 255) / 256, blk>>>(w_qkv, (__half2*)wqh, (__half2*)wql, nq4);
    int np4 = (256 * 512) / 4;
    split_pair_k<<<(np4 + 255) / 256, blk>>>(w_proj, (__half2*)wph, (__half2*)wpl, np4);

    // 1) qkv = w_qkv(768x256) @ x[b](256x4096)
    gemm_fp16x2<<<dim3(32, 6, B_), blk, GEMM_DSMEM>>>(
        wqh, wql, xh, xl, qkv, 768, HWN, 256, nullptr, nullptr, nullptr, nullptr);
    // 2) fused dw 5x5 + grouped pw
    dwpw_k<<<dim3(4, 4, B_ * 96), blk>>>(w_dw, w_pw);
    // 3) attention
    cudaMemsetAsync(kv, 0, B_ * 64 * 72 * sizeof(float));
    att1_k<<<dim3(B_ * 64, 4), blk>>>();
    att2_k<<<dim3(B_ * 64, 4), blk>>>();
    // 4) proj + BN
    gemm_fp16x2<<<dim3(32, 2, B_), blk, GEMM_DSMEM>>>(
        wph, wpl, ath, atl, out, 256, HWN, 512, gm, bt, mn, vr);
}

// round 7
// speedup vs baseline: 3.8180x; 1.3822x over previous
#include <cuda_runtime.h>
#include <cuda_fp16.h>
#include <cstdint>

#define B_   8
#define HWN  4096
#define C3   768
#define CATT 512

// fp32 intermediates
__device__ float g_qkv[B_ * C3 * HWN];
__device__ float g_pw [B_ * C3 * HWN];
__device__ float g_kv [B_ * 64 * 72];

// fp16 split planes (GEMM operands)
__device__ __half g_xh [B_ * 256 * HWN];
__device__ __half g_xl [B_ * 256 * HWN];
__device__ __half g_ath[B_ * CATT * HWN];
__device__ __half g_atl[B_ * CATT * HWN];
__device__ __half g_wqh[768 * 256];
__device__ __half g_wql[768 * 256];
__device__ __half g_wph[256 * 512];
__device__ __half g_wpl[256 * 512];

// ===========================================================================
// helpers
// ===========================================================================
__device__ __forceinline__ uint32_t smem_u32(const void* p) {
    uint32_t a;
    asm("{ .reg .u64 t; cvta.to.shared.u64 t, %1; cvt.u32.u64 %0, t; }"
        : "=r"(a) : "l"(p));
    return a;
}
__device__ __forceinline__ void cpa16(uint32_t dst, const void* src) {
    asm volatile("cp.async.cg.shared.global [%0], [%1], 16;"
                 :: "r"(dst), "l"(src) : "memory");
}
#define CP_COMMIT() asm volatile("cp.async.commit_group;" ::: "memory")
#define CP_WAIT1()  asm volatile("cp.async.wait_group 1;" ::: "memory")

#define LDSM(r0,r1,r2,r3,a) \
    asm volatile("ldmatrix.sync.aligned.m8n8.x4.shared.b16 {%0,%1,%2,%3}, [%4];" \
        : "=r"(r0),"=r"(r1),"=r"(r2),"=r"(r3) : "r"(a))
#define LDSMT(r0,r1,r2,r3,a) \
    asm volatile("ldmatrix.sync.aligned.m8n8.x4.trans.shared.b16 {%0,%1,%2,%3}, [%4];" \
        : "=r"(r0),"=r"(r1),"=r"(r2),"=r"(r3) : "r"(a))
#define MMA(acc_, a_, b0_, b1_) \
    asm volatile("mma.sync.aligned.m16n8k16.row.col.f32.f16.f16.f32 " \
        "{%0,%1,%2,%3}, {%4,%5,%6,%7}, {%8,%9}, {%0,%1,%2,%3};" \
        : "+f"(acc_[0]), "+f"(acc_[1]), "+f"(acc_[2]), "+f"(acc_[3]) \
        : "r"(a_[0]), "r"(a_[1]), "r"(a_[2]), "r"(a_[3]), "r"(b0_), "r"(b1_))

// ===========================================================================
// split fp32 -> fp16 hi/lo planes. n4 = element count / 4.
// ===========================================================================
__global__ __launch_bounds__(256) void split_pair_k(
    const float* __restrict__ src, __half2* __restrict__ h2,
    __half2* __restrict__ l2, int n4)
{
    int i = blockIdx.x * 256 + threadIdx.x;
    if (i >= n4) return;
    float4 v = reinterpret_cast<const float4*>(src)[i];
    float f[4] = {v.x, v.y, v.z, v.w};
    __half hh[4], ll[4];
#pragma unroll
    for (int j = 0; j < 4; j++) {
        hh[j] = __float2half_rn(f[j]);
        ll[j] = __float2half_rn(f[j] - __half2float(hh[j]));
    }
    h2[2 * i]     = __halves2half2(hh[0], hh[1]);
    h2[2 * i + 1] = __halves2half2(hh[2], hh[3]);
    l2[2 * i]     = __halves2half2(ll[0], ll[1]);
    l2[2 * i + 1] = __halves2half2(ll[2], ll[3]);
}

// ===========================================================================
// fp16x2-split GEMM, K-tile 32: C[z](MxN) = A(MxK) @ B[z](KxN), fp32 acc,
// 3 products per k16. 128x128 block tile, 8 warps (2m x 4n), 3-stage cp.async.
// A smem: 64B rows, XOR-16B swizzle (row>>1)&3. B smem: 272B rows (padded).
// ===========================================================================
#define AOFF_L 8192
#define BOFF_H 16384
#define BOFF_L 25088
#define STG    33792
#define GEMM_DSMEM (3 * STG)

__global__ __launch_bounds__(256, 2) void gemm_fp16x2(
    const __half* __restrict__ Ah, const __half* __restrict__ Al,
    const __half* __restrict__ Bh, const __half* __restrict__ Bl,
    float* __restrict__ Csrc, int M, int N, int K,
    const float* __restrict__ gamma, const float* __restrict__ beta,
    const float* __restrict__ mean,  const float* __restrict__ var)
{
    extern __shared__ char dsm[];
    const uint32_t sb = smem_u32(dsm);

    const int tid = threadIdx.x, lane = tid & 31, warp = tid >> 5;
    const int wm = warp >> 2, wn = warp & 3;
    const int gr = lane >> 2, gc = lane & 3;

    const size_t bz = (size_t)blockIdx.z * K * N;
    float* Cm = Csrc + (size_t)blockIdx.z * M * N;

    // ---- cp.async mappings ----
    // A: thread -> row = tid>>1, 2 chunks (16B = 8 halves) at c = (tid&1)*2 + {0,1}
    const int arow = tid >> 1;
    const int acb  = (tid & 1) * 2;
    const __half* aSrcH = Ah + (size_t)(blockIdx.y * 128 + arow) * K;
    const __half* aSrcL = Al + (size_t)(blockIdx.y * 128 + arow) * K;
    // B: thread -> 2 chunks q = tid*2+{0,1}; krow = q>>4, seg = q&15
    const __half* bSrcH = Bh + bz + blockIdx.x * 128;
    const __half* bSrcL = Bl + bz + blockIdx.x * 128;

    auto issue = [&](int kt) {
        uint32_t st = sb + (kt % 3) * STG;
        int kbase = kt * 32;
#pragma unroll
        for (int j = 0; j < 2; j++) {
            int c = acb + j;
            uint32_t ad = st + arow * 64 + ((c ^ ((arow >> 1) & 3)) * 16);
            cpa16(ad,          aSrcH + kbase + c * 8);
            cpa16(ad + AOFF_L, aSrcL + kbase + c * 8);
        }
#pragma unroll
        for (int j = 0; j < 2; j++) {
            int q = tid * 2 + j;
            int krow = q >> 4, seg = q & 15;
            uint32_t bd = st + krow * 272 + seg * 16;
            const size_t so = (size_t)(kbase + krow) * N + seg * 8;
            cpa16(bd + BOFF_H, bSrcH + so);
            cpa16(bd + BOFF_L, bSrcL + so);
        }
    };

    float acc[4][4][4];
#pragma unroll
    for (int mt = 0; mt < 4; mt++)
#pragma unroll
        for (int nt = 0; nt < 4; nt++)
#pragma unroll
            for (int i = 0; i < 4; i++) acc[mt][nt][i] = 0.f;

    const int nk = K / 32;
    issue(0); CP_COMMIT();
    issue(1); CP_COMMIT();

    // fragment address components
    const uint32_t brow = (lane & 7) + 8 * ((lane >> 3) & 1);   // B k-row within 16
    const uint32_t bn   = 8 * (lane >> 4);                      // B n half-sel
    const int arl = lane & 15;                                  // A row within 16
    const int ach = lane >> 4;                                  // A chunk half-sel

    for (int kt = 0; kt < nk; kt++) {
        CP_WAIT1();
        __syncthreads();
        if (kt + 2 < nk) issue(kt + 2);
        CP_COMMIT();

        const uint32_t st = sb + (kt % 3) * STG;

#pragma unroll
        for (int ks = 0; ks < 2; ks++) {
            uint32_t bfr[2][2][4];   // [plane][ng][reg]
#pragma unroll
            for (int ng = 0; ng < 2; ng++) {
                uint32_t ad = st + BOFF_H + (ks * 16 + brow) * 272
                            + (wn * 32 + ng * 16 + bn) * 2;
                LDSMT(bfr[0][ng][0], bfr[0][ng][1], bfr[0][ng][2], bfr[0][ng][3], ad);
                LDSMT(bfr[1][ng][0], bfr[1][ng][1], bfr[1][ng][2], bfr[1][ng][3],
                      ad + (BOFF_L - BOFF_H));
            }
#pragma unroll
            for (int mt = 0; mt < 4; mt++) {
                int rA = wm * 64 + mt * 16 + arl;
                int c = ks * 2 + ach;
                uint32_t ma = st + rA * 64 + ((c ^ ((rA >> 1) & 3)) * 16);
                uint32_t ah[4], al[4];
                LDSM(ah[0], ah[1], ah[2], ah[3], ma);
                LDSM(al[0], al[1], al[2], al[3], ma + AOFF_L);
#pragma unroll
                for (int ng = 0; ng < 2; ng++)
#pragma unroll
                    for (int j = 0; j < 2; j++) {
                        int nt = 2 * ng + j;
                        MMA(acc[mt][nt], ah, bfr[1][ng][2 * j], bfr[1][ng][2 * j + 1]);
                        MMA(acc[mt][nt], al, bfr[0][ng][2 * j], bfr[0][ng][2 * j + 1]);
                        MMA(acc[mt][nt], ah, bfr[0][ng][2 * j], bfr[0][ng][2 * j + 1]);
                    }
            }
        }
    }

    // epilogue
#pragma unroll
    for (int mt = 0; mt < 4; mt++) {
        int r0 = blockIdx.y * 128 + wm * 64 + mt * 16 + gr;
        int r1 = r0 + 8;
        float sc0 = 1.f, bi0 = 0.f, sc1 = 1.f, bi1 = 0.f;
        if (gamma) {
            float i0 = gamma[r0] * rsqrtf(var[r0] + 1e-5f);
            float i1 = gamma[r1] * rsqrtf(var[r1] + 1e-5f);
            sc0 = i0; bi0 = beta[r0] - mean[r0] * i0;
            sc1 = i1; bi1 = beta[r1] - mean[r1] * i1;
        }
#pragma unroll
        for (int nt = 0; nt < 4; nt++) {
            int col = blockIdx.x * 128 + wn * 32 + nt * 8 + gc * 2;
            float2 v0 = make_float2(acc[mt][nt][0] * sc0 + bi0, acc[mt][nt][1] * sc0 + bi0);
            float2 v1 = make_float2(acc[mt][nt][2] * sc1 + bi1, acc[mt][nt][3] * sc1 + bi1);
            *reinterpret_cast<float2*>(Cm + (size_t)r0 * N + col) = v0;
            *reinterpret_cast<float2*>(Cm + (size_t)r1 * N + col) = v1;
        }
    }
}

// ===========================================================================
// Fused depthwise 5x5 (pad 2) + grouped pointwise (96 groups, 8->8).
// 32x32 pixel tiles, float4 I/O, register sliding window.
// ===========================================================================
__global__ __launch_bounds__(256) void dwpw_k(const float* __restrict__ w_dw,
                                              const float* __restrict__ w_pw)
{
    const int bz = blockIdx.z;
    const int g = bz % 96, b = bz / 96;

    __shared__ float t[8][36][40];
    __shared__ float wd[8][25];
    __shared__ float wp[64];

    const int tid = threadIdx.x;
    const int tx4 = (tid & 7) * 4, ty = tid >> 3;
    const int x0 = (blockIdx.x & 1) * 32, y0 = (blockIdx.x >> 1) * 32;

    const float* ip = g_qkv + ((size_t)b * C3 + g * 8) * HWN;

    if (tid < 200) wd[tid / 25][tid % 25] = w_dw[g * 200 + tid];
    if (tid < 64)  wp[tid] = w_pw[g * 64 + tid];

    // load 8ch x 36y x 40x (float4, halo 2 + alignment pad)
    for (int i = tid; i < 2880; i += 256) {
        int ch = i / 360, rem = i % 360;
        int yy = rem / 10, vx = rem % 10;
        int gy = y0 + yy - 2, gx = x0 + vx * 4 - 4;
        float4 v = make_float4(0.f, 0.f, 0.f, 0.f);
        if ((unsigned)gy < 64u && (unsigned)gx < 64u)
            v = *reinterpret_cast<const float4*>(ip + ch * HWN + gy * 64 + gx);
        *reinterpret_cast<float4*>(&t[ch][yy][vx * 4]) = v;
    }
    __syncthreads();

    float dv[8][4];
#pragma unroll
    for (int ch = 0; ch < 8; ch++) {
        float a0 = 0.f, a1 = 0.f, a2 = 0.f, a3 = 0.f;
#pragma unroll
        for (int ky = 0; ky < 5; ky++) {
            const float* row = &t[ch][ty + ky][tx4 + 2];
            float r[8];
#pragma unroll
            for (int i = 0; i < 8; i++) r[i] = row[i];
#pragma unroll
            for (int kx = 0; kx < 5; kx++) {
                float w = wd[ch][ky * 5 + kx];
                a0 += r[kx] * w; a1 += r[kx + 1] * w;
                a2 += r[kx + 2] * w; a3 += r[kx + 3] * w;
            }
        }
        dv[ch][0] = a0; dv[ch][1] = a1; dv[ch][2] = a2; dv[ch][3] = a3;
    }

    float* op = g_pw + ((size_t)b * C3 + g * 8) * HWN + (y0 + ty) * 64 + x0 + tx4;
#pragma unroll
    for (int o = 0; o < 8; o++) {
        float4 s = make_float4(0.f, 0.f, 0.f, 0.f);
#pragma unroll
        for (int i = 0; i < 8; i++) {
            float w = wp[o * 8 + i];
            s.x += dv[i][0] * w; s.y += dv[i][1] * w;
            s.z += dv[i][2] * w; s.w += dv[i][3] * w;
        }
        *reinterpret_cast<float4*>(op + o * HWN) = s;
    }
}

// ===========================================================================
// Attention pass 1: kv[d][e] partial sums per (b,h), 4 px/thread via float4.
// ===========================================================================
__global__ __launch_bounds__(256) void att1_k()
{
    const int bh = blockIdx.x;
    const int h = bh & 63, b = bh >> 6;

    const float* src = (h < 32)
        ? g_qkv + ((size_t)b * C3 + h * 24) * HWN
        : g_pw  + ((size_t)b * C3 + (h - 32) * 24) * HWN;

    float acc[72];
#pragma unroll
    for (int i = 0; i < 72; i++) acc[i] = 0.f;

    const int hw = blockIdx.y * 1024 + threadIdx.x * 4;
    float4 kk[8], vv[8];
#pragma unroll
    for (int d = 0; d < 8; d++) {
        float4 v = *reinterpret_cast<const float4*>(src + (8 + d) * HWN + hw);
        kk[d] = make_float4(fmaxf(v.x, 0.f), fmaxf(v.y, 0.f),
                            fmaxf(v.z, 0.f), fmaxf(v.w, 0.f));
    }
#pragma unroll
    for (int e = 0; e < 8; e++)
        vv[e] = *reinterpret_cast<const float4*>(src + (16 + e) * HWN + hw);

#pragma unroll
    for (int d = 0; d < 8; d++) {
#pragma unroll
        for (int e = 0; e < 8; e++)
            acc[d * 9 + e] += kk[d].x * vv[e].x + kk[d].y * vv[e].y
                            + kk[d].z * vv[e].z + kk[d].w * vv[e].w;
        acc[d * 9 + 8] += kk[d].x + kk[d].y + kk[d].z + kk[d].w;
    }

    __shared__ float red[8][72];
    const int lane = threadIdx.x & 31, warp = threadIdx.x >> 5;
#pragma unroll
    for (int i = 0; i < 72; i++) {
        float v = acc[i];
#pragma unroll
        for (int o = 16; o > 0; o >>= 1) v += __shfl_down_sync(0xffffffffu, v, o);
        if (lane == 0) red[warp][i] = v;
    }
    __syncthreads();
    if (threadIdx.x < 72) {
        float s = 0.f;
#pragma unroll
        for (int w = 0; w < 8; w++) s += red[w][threadIdx.x];
        atomicAdd(&g_kv[bh * 72 + threadIdx.x], s);
    }
}

// ===========================================================================
// Attention pass 2: out = relu(q) @ kv, normalize; write fp16 hi/lo planes.
// 4 px/thread.
// ===========================================================================
__global__ __launch_bounds__(256) void att2_k()
{
    const int bh = blockIdx.x;
    const int h = bh & 63, b = bh >> 6;

    const float* src = (h < 32)
        ? g_qkv + ((size_t)b * C3 + h * 24) * HWN
        : g_pw  + ((size_t)b * C3 + (h - 32) * 24) * HWN;

    __shared__ float kvm[72];
    if (threadIdx.x < 72) kvm[threadIdx.x] = g_kv[bh * 72 + threadIdx.x];
    __syncthreads();

    const size_t dbase = ((size_t)b * CATT + h * 8) * HWN;
    const int hw = blockIdx.y * 1024 + threadIdx.x * 4;

    float4 q[8];
#pragma unroll
    for (int d = 0; d < 8; d++) {
        float4 v = *reinterpret_cast<const float4*>(src + d * HWN + hw);
        q[d] = make_float4(fmaxf(v.x, 0.f), fmaxf(v.y, 0.f),
                           fmaxf(v.z, 0.f), fmaxf(v.w, 0.f));
    }
    // denominator
    float4 den = make_float4(0.f, 0.f, 0.f, 0.f);
#pragma unroll
    for (int d = 0; d < 8; d++) {
        float w = kvm[d * 9 + 8];
        den.x += q[d].x * w; den.y += q[d].y * w;
        den.z += q[d].z * w; den.w += q[d].w * w;
    }
    float4 inv;
    inv.x = 1.f / (den.x + 1e-15f); inv.y = 1.f / (den.y + 1e-15f);
    inv.z = 1.f / (den.z + 1e-15f); inv.w = 1.f / (den.w + 1e-15f);

#pragma unroll
    for (int e = 0; e < 8; e++) {
        float4 o = make_float4(0.f, 0.f, 0.f, 0.f);
#pragma unroll
        for (int d = 0; d < 8; d++) {
            float w = kvm[d * 9 + e];
            o.x += q[d].x * w; o.y += q[d].y * w;
            o.z += q[d].z * w; o.w += q[d].w * w;
        }
        float val[4] = {o.x * inv.x, o.y * inv.y, o.z * inv.z, o.w * inv.w};
        __half hh[4], ll[4];
#pragma unroll
        for (int j = 0; j < 4; j++) {
            hh[j] = __float2half_rn(val[j]);
            ll[j] = __float2half_rn(val[j] - __half2float(hh[j]));
        }
        __half2* ph = reinterpret_cast<__half2*>(&g_ath[dbase + e * HWN + hw]);
        __half2* pl = reinterpret_cast<__half2*>(&g_atl[dbase + e * HWN + hw]);
        ph[0] = __halves2half2(hh[0], hh[1]);
        ph[1] = __halves2half2(hh[2], hh[3]);
        pl[0] = __halves2half2(ll[0], ll[1]);
        pl[1] = __halves2half2(ll[2], ll[3]);
    }
}

// ===========================================================================
extern "C" void kernel_launch(void* const* d_in, const int* in_sizes, int n_in,
                              void* d_out, int out_size)
{
    const float* x      = (const float*)d_in[0];
    const float* w_qkv  = (const float*)d_in[1];
    const float* w_dw   = (const float*)d_in[2];
    const float* w_pw   = (const float*)d_in[3];
    const float* w_proj = (const float*)d_in[4];
    const float* gm     = (const float*)d_in[5];
    const float* bt     = (const float*)d_in[6];
    const float* mn     = (const float*)d_in[7];
    const float* vr     = (const float*)d_in[8];
    float* out = (float*)d_out;

    float *qkv, *kv;
    __half *xh, *xl, *ath, *atl, *wqh, *wql, *wph, *wpl;
    cudaGetSymbolAddress((void**)&qkv, g_qkv);
    cudaGetSymbolAddress((void**)&kv,  g_kv);
    cudaGetSymbolAddress((void**)&xh,  g_xh);
    cudaGetSymbolAddress((void**)&xl,  g_xl);
    cudaGetSymbolAddress((void**)&ath, g_ath);
    cudaGetSymbolAddress((void**)&atl, g_atl);
    cudaGetSymbolAddress((void**)&wqh, g_wqh);
    cudaGetSymbolAddress((void**)&wql, g_wql);
    cudaGetSymbolAddress((void**)&wph, g_wph);
    cudaGetSymbolAddress((void**)&wpl, g_wpl);

    cudaFuncSetAttribute(gemm_fp16x2, cudaFuncAttributeMaxDynamicSharedMemorySize,
                         GEMM_DSMEM);

    dim3 blk(256);

    // 0) split operands into fp16 hi/lo planes
    int nx4 = (B_ * 256 * HWN) / 4;
    split_pair_k<<<(nx4 + 255) / 256, blk>>>(x, (__half2*)xh, (__half2*)xl, nx4);
    int nq4 = (768 * 256) / 4;
    split_pair_k<<<(nq4 + 255) / 256, blk>>>(w_qkv, (__half2*)wqh, (__half2*)wql, nq4);
    int np4 = (256 * 512) / 4;
    split_pair_k<<<(np4 + 255) / 256, blk>>>(w_proj, (__half2*)wph, (__half2*)wpl, np4);

    // 1) qkv = w_qkv(768x256) @ x[b](256x4096)
    gemm_fp16x2<<<dim3(32, 6, B_), blk, GEMM_DSMEM>>>(
        wqh, wql, xh, xl, qkv, 768, HWN, 256, nullptr, nullptr, nullptr, nullptr);
    // 2) fused dw 5x5 + grouped pw (32x32 tiles)
    dwpw_k<<<dim3(4, 1, B_ * 96), blk>>>(w_dw, w_pw);
    // 3) attention
    cudaMemsetAsync(kv, 0, B_ * 64 * 72 * sizeof(float));
    att1_k<<<dim3(B_ * 64, 4), blk>>>();
    att2_k<<<dim3(B_ * 64, 4), blk>>>();
    // 4) proj + BN
    gemm_fp16x2<<<dim3(32, 2, B_), blk, GEMM_DSMEM>>>(
        wph, wpl, ath, atl, out, 256, HWN, 512, gm, bt, mn, vr);
}